// round 6
// baseline (speedup 1.0000x reference)
#include <cuda_runtime.h>
#include <math.h>

#define Ldim 128
#define Ddim 512
#define Mdim 2048
#define NTAIL 127

typedef unsigned long long ull;

// packed dual-fp32 FMA: d.lanes += a.lanes * b.lanes (IEEE fp32 per lane)
#define FMA2(d, a, b) asm("fma.rn.f32x2 %0, %1, %2, %0;" : "+l"(d) : "l"(a), "l"(b))
#define UNPK(lo, hi, v) asm("mov.b64 {%0, %1}, %2;" : "=f"(lo), "=f"(hi) : "l"(v))

__device__ float g_A[Ldim*Ddim];
__device__ float g_Bm[Ldim*Ddim];
__device__ float g_T[Ldim*Mdim];
__device__ float g_U[Ldim*Mdim];
__device__ float g_G[5][Ldim*Ddim];
__device__ float g_S[Ddim*Ddim];
__device__ float g_P0[Ddim*Ddim];
__device__ float g_P1[Ddim*Ddim];
__device__ float g_Delta[Ldim*Ldim];
__device__ float g_DtD[Ldim*Ldim];
__device__ float g_Q0[Ldim*Ldim];
__device__ float g_Q1[Ldim*Ldim];
__device__ float g_ytail[NTAIL];
__device__ float g_red[4];
__device__ float g_scal[4];   // [0]=maxeig(xxT) [1]=maxeig(DtD) [2]=tau [3]=thr
__device__ int   g_done;
__device__ int   g_cntg[8];   // per-y-stripe counters for grad kernel
__device__ int   g_cntf;      // counter for fwd kernel

// ---------------- init / constants ----------------
__global__ void k_init(const float* __restrict__ mask, const float* __restrict__ py,
                       const float* __restrict__ y0) {
    int idx = blockIdx.x * blockDim.x + threadIdx.x;
    if (idx < Ldim*Ddim) { g_A[idx] = 0.f; g_Bm[idx] = 0.f; }
    if (idx < Ldim*Mdim) { g_U[idx] = -mask[idx] * py[idx]; }
    if (idx < NTAIL)     { g_ytail[idx] = y0[Mdim + idx]; }
    if (idx < 8)         { g_cntg[idx] = 0; }
    if (idx == 8)        { g_cntf = 0; }
    if (idx == 9)        { g_done = 0; }
}

__global__ void k_delta() {
    int idx = blockIdx.x * blockDim.x + threadIdx.x;
    if (idx < Ldim*Ldim) {
        int p = idx >> 7, c = idx & 127;
        float v = (c == p) ? 1.f : ((c == p-1) ? -2.f : ((c == p-2) ? 1.f : 0.f));
        if (p == 0 && c == 0) v = 0.f;
        if (p == 1 && c == 0) v = -1.f;
        g_Delta[idx] = v;
    }
}

__global__ void k_dtd() {
    int idx = blockIdx.x * blockDim.x + threadIdx.x;
    if (idx < Ldim*Ldim) {
        int i = idx >> 7, j = idx & 127;
        float s = 0.f;
        for (int p = 0; p < 128; p++) s += g_Delta[p*128 + i] * g_Delta[p*128 + j];
        g_DtD[idx] = s;
    }
}

// ---------------- packed NT GEMM (precompute): C = (A.B^T) * sc, C n x n ----------------
__global__ void __launch_bounds__(256) gemm_nt2(const float* __restrict__ A,
                                                const float* __restrict__ B,
                                                float* __restrict__ C,
                                                int n, int K, int scaled) {
    __shared__ __align__(16) float As[2][32][68];
    __shared__ __align__(16) float Bs[2][32][68];
    int i0 = blockIdx.x * 32, j0 = blockIdx.y * 64;
    int tid = threadIdx.x;
    int ti = tid >> 4, tj = tid & 15;
    int tr = tid >> 5, tc = tid & 31;
    ull acc00 = 0, acc01 = 0, acc10 = 0, acc11 = 0;
    float ar[4], br[8];
    int nk = K >> 5;

    auto load_regs = [&](int kt) {
        int k0 = kt * 32;
        #pragma unroll
        for (int r = 0; r < 4; r++) ar[r] = A[(i0 + tr + 8*r) * K + k0 + tc];
        #pragma unroll
        for (int r = 0; r < 8; r++) br[r] = B[(j0 + tr + 8*r) * K + k0 + tc];
    };
    auto store_smem = [&](int b) {
        #pragma unroll
        for (int r = 0; r < 4; r++) {
            float2 v = make_float2(ar[r], ar[r]);
            *(float2*)&As[b][tc][2*(tr + 8*r)] = v;
        }
        #pragma unroll
        for (int r = 0; r < 8; r++) Bs[b][tc][tr + 8*r] = br[r];
    };

    load_regs(0); store_smem(0); __syncthreads();
    for (int kt = 0; kt < nk; kt++) {
        int b = kt & 1;
        if (kt + 1 < nk) load_regs(kt + 1);
        ull a0 = *(const ull*)&As[b][0][4*ti];
        ull a1 = *(const ull*)&As[b][0][4*ti + 2];
        ulonglong2 bp = *(const ulonglong2*)&Bs[b][0][4*tj];
        #pragma unroll
        for (int kk = 0; kk < 32; kk++) {
            ull a0n = 0, a1n = 0; ulonglong2 bpn;
            if (kk < 31) {
                a0n = *(const ull*)&As[b][kk+1][4*ti];
                a1n = *(const ull*)&As[b][kk+1][4*ti + 2];
                bpn = *(const ulonglong2*)&Bs[b][kk+1][4*tj];
            }
            FMA2(acc00, a0, bp.x); FMA2(acc01, a0, bp.y);
            FMA2(acc10, a1, bp.x); FMA2(acc11, a1, bp.y);
            if (kk < 31) { a0 = a0n; a1 = a1n; bp = bpn; }
        }
        if (kt + 1 < nk) { store_smem((kt + 1) & 1); __syncthreads(); }
    }
    float sc = 1.f;
    if (scaled) { float t = g_red[0]; sc = 1.f / (t * t); }
    float4 r0, r1;
    UNPK(r0.x, r0.y, acc00); UNPK(r0.z, r0.w, acc01);
    UNPK(r1.x, r1.y, acc10); UNPK(r1.z, r1.w, acc11);
    r0.x *= sc; r0.y *= sc; r0.z *= sc; r0.w *= sc;
    r1.x *= sc; r1.y *= sc; r1.z *= sc; r1.w *= sc;
    int i = i0 + 2*ti, j = j0 + 4*tj;
    *(float4*)&C[i*n + j]       = r0;
    *(float4*)&C[(i+1)*n + j]   = r1;
}

// ---------------- trace ----------------
__global__ void k_trace(const float* __restrict__ m, int n) {
    __shared__ float sh[512];
    int t = threadIdx.x;
    sh[t] = (t < n) ? m[t*n + t] : 0.f;
    __syncthreads();
    for (int off = 256; off > 0; off >>= 1) {
        if (t < off) sh[t] += sh[t + off];
        __syncthreads();
    }
    if (t == 0) g_red[0] = sh[0];
}

// ---------------- Rayleigh: v = P*r, lambda = (v^T S v)/(v^T v) ----------------
__global__ void k_rayleigh(const float* __restrict__ P, const float* __restrict__ S,
                           int n, int slot) {
    __shared__ float v[512];
    __shared__ float r1[512], r2[512];
    int t = threadIdx.x;
    float s = 0.f;
    for (int j = 0; j < n; j++) s += P[t*n + j] * (sinf(0.7331f * j + 0.1234f) + 1.5f);
    v[t] = s;
    __syncthreads();
    float w = 0.f;
    for (int j = 0; j < n; j++) w += S[t*n + j] * v[j];
    r1[t] = v[t] * w;
    r2[t] = v[t] * v[t];
    __syncthreads();
    for (int off = n >> 1; off > 0; off >>= 1) {
        if (t < off) { r1[t] += r1[t+off]; r2[t] += r2[t+off]; }
        __syncthreads();
    }
    if (t == 0) g_scal[slot] = r1[0] / r2[0];
}

__global__ void k_scalars() {
    float tau = 1.0f / (2.0f * (g_scal[0] + 0.1f * g_scal[1]));
    float lam2 = (tau * 0.1f > 0.1f) ? (0.1f / tau) : 0.1f;
    g_scal[2] = tau;
    g_scal[3] = tau * lam2;
}

// ---------------- fused gradient + prox/momentum update ----------------
__global__ void __launch_bounds__(256) k_grad(const float* __restrict__ x, float coeff) {
    if (g_done) return;
    __shared__ __align__(16) float Us[2][32][68];
    __shared__ __align__(16) float Xs[2][32][68];
    __shared__ int s_last;
    int z = blockIdx.z;
    int i0 = blockIdx.x * 32, j0 = blockIdx.y * 64;
    int tid = threadIdx.x;
    int ti = tid >> 4, tj = tid & 15;
    int tr = tid >> 5, tc = tid & 31;
    int rr = tid >> 6, cc = tid & 63;
    ull acc00 = 0, acc01 = 0, acc10 = 0, acc11 = 0;
    float ur[4], xr[8];
    int nk = (z < 4) ? 16 : 4;

    auto load_regs = [&](int kt) {
        if (z < 4) {
            int m0 = z * 512 + kt * 32;
            #pragma unroll
            for (int r = 0; r < 4; r++) ur[r] = g_U[(i0 + tr + 8*r) * Mdim + m0 + tc];
            #pragma unroll
            for (int r = 0; r < 8; r++) xr[r] = x[(j0 + tr + 8*r) * Mdim + m0 + tc];
        } else {
            int p0 = kt * 32;
            #pragma unroll
            for (int r = 0; r < 4; r++) ur[r] = g_DtD[(i0 + tr + 8*r) * Ldim + p0 + tc];
            #pragma unroll
            for (int r = 0; r < 8; r++) xr[r] = g_A[(p0 + rr + 4*r) * Ddim + j0 + cc];
        }
    };
    auto store_smem = [&](int b) {
        #pragma unroll
        for (int r = 0; r < 4; r++) {
            float2 v = make_float2(ur[r], ur[r]);
            *(float2*)&Us[b][tc][2*(tr + 8*r)] = v;
        }
        if (z < 4) {
            #pragma unroll
            for (int r = 0; r < 8; r++) Xs[b][tc][tr + 8*r] = xr[r];
        } else {
            #pragma unroll
            for (int r = 0; r < 8; r++) Xs[b][rr + 4*r][cc] = xr[r];
        }
    };

    load_regs(0); store_smem(0); __syncthreads();
    for (int kt = 0; kt < nk; kt++) {
        int b = kt & 1;
        if (kt + 1 < nk) load_regs(kt + 1);
        ull a0 = *(const ull*)&Us[b][0][4*ti];
        ull a1 = *(const ull*)&Us[b][0][4*ti + 2];
        ulonglong2 bp = *(const ulonglong2*)&Xs[b][0][4*tj];
        #pragma unroll
        for (int kk = 0; kk < 32; kk++) {
            ull a0n = 0, a1n = 0; ulonglong2 bpn;
            if (kk < 31) {
                a0n = *(const ull*)&Us[b][kk+1][4*ti];
                a1n = *(const ull*)&Us[b][kk+1][4*ti + 2];
                bpn = *(const ulonglong2*)&Xs[b][kk+1][4*tj];
            }
            FMA2(acc00, a0, bp.x); FMA2(acc01, a0, bp.y);
            FMA2(acc10, a1, bp.x); FMA2(acc11, a1, bp.y);
            if (kk < 31) { a0 = a0n; a1 = a1n; bp = bpn; }
        }
        if (kt + 1 < nk) { store_smem((kt + 1) & 1); __syncthreads(); }
    }
    float sc = (z == 4) ? 0.1f : 1.f;
    float4 r0, r1;
    UNPK(r0.x, r0.y, acc00); UNPK(r0.z, r0.w, acc01);
    UNPK(r1.x, r1.y, acc10); UNPK(r1.z, r1.w, acc11);
    r0.x *= sc; r0.y *= sc; r0.z *= sc; r0.w *= sc;
    r1.x *= sc; r1.y *= sc; r1.z *= sc; r1.w *= sc;
    {
        int i = i0 + 2*ti, j = j0 + 4*tj;
        *(float4*)&g_G[z][i*Ddim + j]     = r0;
        *(float4*)&g_G[z][(i+1)*Ddim + j] = r1;
    }

    // ---- stripe-completion gate, then fused update ----
    __threadfence();
    __syncthreads();
    if (tid == 0) s_last = (atomicAdd(&g_cntg[blockIdx.y], 1) == 19) ? 1 : 0;
    __syncthreads();
    if (!s_last) return;
    __threadfence();
    float tau = g_scal[2], thr = g_scal[3];
    int jbase = blockIdx.y * 64;
    for (int e = tid; e < 2048; e += 256) {
        int i = e >> 4, c4 = (e & 15) << 2;
        int off = i * Ddim + jbase + c4;
        float4 g0 = *(float4*)&g_G[0][off];
        float4 g1 = *(float4*)&g_G[1][off];
        float4 g2 = *(float4*)&g_G[2][off];
        float4 g3 = *(float4*)&g_G[3][off];
        float4 g4 = *(float4*)&g_G[4][off];
        float4 a  = *(float4*)&g_A[off];
        float4 bm = *(float4*)&g_Bm[off];
        float4 an, bn;
        {
            float g, zv, az;
            g = g0.x + g1.x + g2.x + g3.x + g4.x; zv = bm.x - tau*g; az = fabsf(zv) - thr;
            an.x = (az > 0.f) ? copysignf(az, zv) : 0.f; bn.x = a.x + coeff * (an.x - a.x);
            g = g0.y + g1.y + g2.y + g3.y + g4.y; zv = bm.y - tau*g; az = fabsf(zv) - thr;
            an.y = (az > 0.f) ? copysignf(az, zv) : 0.f; bn.y = a.y + coeff * (an.y - a.y);
            g = g0.z + g1.z + g2.z + g3.z + g4.z; zv = bm.z - tau*g; az = fabsf(zv) - thr;
            an.z = (az > 0.f) ? copysignf(az, zv) : 0.f; bn.z = a.z + coeff * (an.z - a.z);
            g = g0.w + g1.w + g2.w + g3.w + g4.w; zv = bm.w - tau*g; az = fabsf(zv) - thr;
            an.w = (az > 0.f) ? copysignf(az, zv) : 0.f; bn.w = a.w + coeff * (an.w - a.w);
        }
        *(float4*)&g_A[off]  = an;
        *(float4*)&g_Bm[off] = bn;
    }
    __syncthreads();
    if (tid == 0) g_cntg[blockIdx.y] = 0;
}

// ---------------- fused forward GEMM + residual + convergence ----------------
__global__ void __launch_bounds__(256) k_fwd(const float* __restrict__ x,
                                             const float* __restrict__ py,
                                             const float* __restrict__ mask) {
    if (g_done) return;
    __shared__ __align__(16) float As[2][32][68];
    __shared__ __align__(16) float Xs[2][32][68];
    __shared__ int s_last;
    __shared__ float s_diag[128], s_r1[128], s_r2[128];
    int i0 = blockIdx.x * 32, m0 = blockIdx.y * 64;
    int tid = threadIdx.x;
    int ti = tid >> 4, tj = tid & 15;
    int tr = tid >> 5, tc = tid & 31;
    int rr = tid >> 6, cc = tid & 63;
    ull acc00 = 0, acc01 = 0, acc10 = 0, acc11 = 0;
    float ar[4], xr[8];

    auto load_regs = [&](int kt) {
        int k0 = kt * 32;
        #pragma unroll
        for (int r = 0; r < 4; r++) ar[r] = g_A[(i0 + tr + 8*r) * Ddim + k0 + tc];
        #pragma unroll
        for (int r = 0; r < 8; r++) xr[r] = x[(k0 + rr + 4*r) * Mdim + m0 + cc];
    };
    auto store_smem = [&](int b) {
        #pragma unroll
        for (int r = 0; r < 4; r++) {
            float2 v = make_float2(ar[r], ar[r]);
            *(float2*)&As[b][tc][2*(tr + 8*r)] = v;
        }
        #pragma unroll
        for (int r = 0; r < 8; r++) Xs[b][rr + 4*r][cc] = xr[r];
    };

    load_regs(0); store_smem(0); __syncthreads();
    for (int kt = 0; kt < 16; kt++) {
        int b = kt & 1;
        if (kt + 1 < 16) load_regs(kt + 1);
        ull a0 = *(const ull*)&As[b][0][4*ti];
        ull a1 = *(const ull*)&As[b][0][4*ti + 2];
        ulonglong2 bp = *(const ulonglong2*)&Xs[b][0][4*tj];
        #pragma unroll
        for (int kk = 0; kk < 32; kk++) {
            ull a0n = 0, a1n = 0; ulonglong2 bpn;
            if (kk < 31) {
                a0n = *(const ull*)&As[b][kk+1][4*ti];
                a1n = *(const ull*)&As[b][kk+1][4*ti + 2];
                bpn = *(const ulonglong2*)&Xs[b][kk+1][4*tj];
            }
            FMA2(acc00, a0, bp.x); FMA2(acc01, a0, bp.y);
            FMA2(acc10, a1, bp.x); FMA2(acc11, a1, bp.y);
            if (kk < 31) { a0 = a0n; a1 = a1n; bp = bpn; }
        }
        if (kt + 1 < 16) { store_smem((kt + 1) & 1); __syncthreads(); }
    }
    float4 r0, r1;
    UNPK(r0.x, r0.y, acc00); UNPK(r0.z, r0.w, acc01);
    UNPK(r1.x, r1.y, acc10); UNPK(r1.z, r1.w, acc11);
    {
        int i = i0 + 2*ti, m = m0 + 4*tj;
        int o0 = i * Mdim + m, o1 = (i+1) * Mdim + m;
        float4 mk0 = *(const float4*)&mask[o0];
        float4 py0 = *(const float4*)&py[o0];
        float4 mk1 = *(const float4*)&mask[o1];
        float4 py1 = *(const float4*)&py[o1];
        *(float4*)&g_T[o0] = r0;
        *(float4*)&g_T[o1] = r1;
        float4 u0 = make_float4(mk0.x*(r0.x - py0.x), mk0.y*(r0.y - py0.y),
                                mk0.z*(r0.z - py0.z), mk0.w*(r0.w - py0.w));
        float4 u1 = make_float4(mk1.x*(r1.x - py1.x), mk1.y*(r1.y - py1.y),
                                mk1.z*(r1.z - py1.z), mk1.w*(r1.w - py1.w));
        *(float4*)&g_U[o0] = u0;
        *(float4*)&g_U[o1] = u1;
    }

    // ---- last block runs the convergence check ----
    __threadfence();
    __syncthreads();
    if (tid == 0) s_last = (atomicAdd(&g_cntf, 1) == 127) ? 1 : 0;
    __syncthreads();
    if (!s_last) return;
    __threadfence();
    float sum = 0.f, yv = 0.f;
    if (tid < NTAIL) {
        for (int i = tid + 1; i < Ldim; i++) sum += g_T[i * Mdim + (Mdim + tid - i)];
        sum /= (float)(NTAIL - tid);
        yv = g_ytail[tid];
    }
    if (tid < 128) {
        float d = (tid < NTAIL) ? (yv - sum) : 0.f;
        s_diag[tid] = sum;
        s_r1[tid] = d * d;
        s_r2[tid] = (tid < NTAIL) ? yv * yv : 0.f;
    }
    __syncthreads();
    for (int off = 64; off > 0; off >>= 1) {
        if (tid < off) { s_r1[tid] += s_r1[tid + off]; s_r2[tid] += s_r2[tid + off]; }
        __syncthreads();
    }
    if (tid == 0) {
        if (sqrtf(s_r1[0] / s_r2[0]) <= 1e-5f) g_done = 1;
        g_cntf = 0;
    }
    if (tid < NTAIL) g_ytail[tid] = s_diag[tid];
}

// ---------------- output: (A@x, A) ----------------
__global__ void k_output(float* __restrict__ out, int out_size) {
    int idx = blockIdx.x * blockDim.x + threadIdx.x;
    if (idx >= out_size) return;
    if (idx < Ldim*Mdim) out[idx] = g_T[idx];
    else if (idx < Ldim*Mdim + Ldim*Ddim) out[idx] = g_A[idx - Ldim*Mdim];
}

extern "C" void kernel_launch(void* const* d_in, const int* in_sizes, int n_in,
                              void* d_out, int out_size) {
    const float* x    = (const float*)d_in[0];
    const float* py   = (const float*)d_in[1];
    const float* mask = (const float*)d_in[2];
    const float* y0   = (const float*)d_in[3];
    float* outp = (float*)d_out;

    void *pS, *pP0, *pP1, *pDtD, *pQ0, *pQ1;
    cudaGetSymbolAddress(&pS,   g_S);
    cudaGetSymbolAddress(&pP0,  g_P0);
    cudaGetSymbolAddress(&pP1,  g_P1);
    cudaGetSymbolAddress(&pDtD, g_DtD);
    cudaGetSymbolAddress(&pQ0,  g_Q0);
    cudaGetSymbolAddress(&pQ1,  g_Q1);

    k_init<<<(Ldim*Mdim + 255)/256, 256>>>(mask, py, y0);
    k_delta<<<(Ldim*Ldim + 255)/256, 256>>>();
    k_dtd<<<(Ldim*Ldim + 255)/256, 256>>>();

    // maxeig(x x^T): S = x x^T, then 10 trace-normalized squarings + Rayleigh
    gemm_nt2<<<dim3(16, 8), 256>>>(x, x, (float*)pS, Ddim, Mdim, 0);
    k_trace<<<1, 512>>>((const float*)pS, Ddim);
    {
        float* bufs[2] = { (float*)pP0, (float*)pP1 };
        const float* cur = (const float*)pS;
        for (int i = 0; i < 10; i++) {
            float* nxt = bufs[i & 1];
            gemm_nt2<<<dim3(16, 8), 256>>>(cur, cur, nxt, Ddim, Ddim, 1);
            k_trace<<<1, 512>>>(nxt, Ddim);
            cur = nxt;
        }
        k_rayleigh<<<1, Ddim>>>(cur, (const float*)pS, Ddim, 0);
    }

    // maxeig(DtD): 17 trace-normalized squarings + Rayleigh
    k_trace<<<1, 512>>>((const float*)pDtD, Ldim);
    {
        float* bufs[2] = { (float*)pQ0, (float*)pQ1 };
        const float* cur = (const float*)pDtD;
        for (int i = 0; i < 17; i++) {
            float* nxt = bufs[i & 1];
            gemm_nt2<<<dim3(4, 2), 256>>>(cur, cur, nxt, Ldim, Ldim, 1);
            k_trace<<<1, 512>>>(nxt, Ldim);
            cur = nxt;
        }
        k_rayleigh<<<1, Ldim>>>(cur, (const float*)pDtD, Ldim, 1);
    }

    k_scalars<<<1, 1>>>();

    // FISTA loop: 2 fused kernels per iteration, device-side early exit
    float a = 1.0f;
    for (int it = 0; it < 200; it++) {
        float anew = (1.0f + sqrtf(1.0f + 4.0f * a * a)) * 0.5f;
        float coeff = (a - 1.0f) / anew;
        a = anew;
        k_grad<<<dim3(4, 8, 5), 256>>>(x, coeff);
        k_fwd<<<dim3(4, 32), 256>>>(x, py, mask);
    }

    k_output<<<(out_size + 255)/256, 256>>>(outp, out_size);
}

// round 7
// speedup vs baseline: 1.1027x; 1.1027x over previous
#include <cuda_runtime.h>
#include <math.h>

#define Ldim 128
#define Ddim 512
#define Mdim 2048
#define NTAIL 127

__device__ float g_A[Ldim*Ddim];
__device__ float g_Bm[Ldim*Ddim];
__device__ float g_T[Ldim*Mdim];
__device__ float g_U[Ldim*Mdim];
__device__ float g_G[5][Ldim*Ddim];
__device__ float g_S[Ddim*Ddim];
__device__ float g_P0[Ddim*Ddim];
__device__ float g_P1[Ddim*Ddim];
__device__ float g_Delta[Ldim*Ldim];
__device__ float g_DtD[Ldim*Ldim];
__device__ float g_Q0[Ldim*Ldim];
__device__ float g_Q1[Ldim*Ldim];
__device__ float g_ytail[NTAIL];
__device__ float g_red[4];
__device__ float g_scal[4];   // [0]=maxeig(xxT) [1]=maxeig(DtD) [2]=tau [3]=thr
__device__ int   g_done;
__device__ int   g_cntg[8];   // per-j-stripe counters for grad kernel
__device__ int   g_cntf;      // counter for fwd kernel

// ---------------- init / constants ----------------
__global__ void k_init(const float* __restrict__ mask, const float* __restrict__ py,
                       const float* __restrict__ y0) {
    int idx = blockIdx.x * blockDim.x + threadIdx.x;
    if (idx < Ldim*Ddim) { g_A[idx] = 0.f; g_Bm[idx] = 0.f; }
    if (idx < Ldim*Mdim) { g_U[idx] = -mask[idx] * py[idx]; }
    if (idx < NTAIL)     { g_ytail[idx] = y0[Mdim + idx]; }
    if (idx < 8)         { g_cntg[idx] = 0; }
    if (idx == 8)        { g_cntf = 0; }
    if (idx == 9)        { g_done = 0; }
}

__global__ void k_delta() {
    int idx = blockIdx.x * blockDim.x + threadIdx.x;
    if (idx < Ldim*Ldim) {
        int p = idx >> 7, c = idx & 127;
        float v = (c == p) ? 1.f : ((c == p-1) ? -2.f : ((c == p-2) ? 1.f : 0.f));
        if (p == 0 && c == 0) v = 0.f;
        if (p == 1 && c == 0) v = -1.f;
        g_Delta[idx] = v;
    }
}

__global__ void k_dtd() {
    int idx = blockIdx.x * blockDim.x + threadIdx.x;
    if (idx < Ldim*Ldim) {
        int i = idx >> 7, j = idx & 127;
        float s = 0.f;
        for (int p = 0; p < 128; p++) s += g_Delta[p*128 + i] * g_Delta[p*128 + j];
        g_DtD[idx] = s;
    }
}

// ---------------- generic NT GEMM (precompute only, R4-proven) ----------------
__global__ void gemm_nt(const float* __restrict__ A, const float* __restrict__ B,
                        float* __restrict__ C, int n, int K) {
    __shared__ float As[32][33];
    __shared__ float Bs[32][33];
    int i0 = blockIdx.x * 32, j0 = blockIdx.y * 32;
    int tid = threadIdx.x;
    int tr = tid >> 5, tc = tid & 31;
    int ti = tid >> 4, tj = tid & 15;
    float a00=0.f, a01=0.f, a10=0.f, a11=0.f;
    for (int k0 = 0; k0 < K; k0 += 32) {
        #pragma unroll
        for (int r = 0; r < 4; r++) {
            As[tc][tr + 8*r] = A[(size_t)(i0 + tr + 8*r) * K + k0 + tc];
            Bs[tc][tr + 8*r] = B[(size_t)(j0 + tr + 8*r) * K + k0 + tc];
        }
        __syncthreads();
        #pragma unroll
        for (int kk = 0; kk < 32; kk++) {
            float av0 = As[kk][2*ti], av1 = As[kk][2*ti+1];
            float bv0 = Bs[kk][2*tj], bv1 = Bs[kk][2*tj+1];
            a00 += av0*bv0; a01 += av0*bv1; a10 += av1*bv0; a11 += av1*bv1;
        }
        __syncthreads();
    }
    int i = i0 + 2*ti, j = j0 + 2*tj;
    C[(size_t)i*n + j]     = a00; C[(size_t)i*n + j+1]     = a01;
    C[(size_t)(i+1)*n + j] = a10; C[(size_t)(i+1)*n + j+1] = a11;
}

// ---------------- trace / normalize ----------------
__global__ void k_trace(const float* __restrict__ m, int n) {
    __shared__ float sh[512];
    int t = threadIdx.x;
    sh[t] = (t < n) ? m[t*n + t] : 0.f;
    __syncthreads();
    for (int off = 256; off > 0; off >>= 1) {
        if (t < off) sh[t] += sh[t + off];
        __syncthreads();
    }
    if (t == 0) g_red[0] = sh[0];
}

__global__ void k_normmat(const float* __restrict__ src, float* __restrict__ dst, int nn) {
    float inv = 1.f / g_red[0];
    int idx = blockIdx.x * blockDim.x + threadIdx.x;
    if (idx < nn) dst[idx] = src[idx] * inv;
}

// ---------------- Rayleigh ----------------
__global__ void k_rayleigh(const float* __restrict__ P, const float* __restrict__ S,
                           int n, int slot) {
    __shared__ float v[512];
    __shared__ float r1[512], r2[512];
    int t = threadIdx.x;
    float s = 0.f;
    for (int j = 0; j < n; j++) s += P[t*n + j] * (sinf(0.7331f * j + 0.1234f) + 1.5f);
    v[t] = s;
    __syncthreads();
    float w = 0.f;
    for (int j = 0; j < n; j++) w += S[t*n + j] * v[j];
    r1[t] = v[t] * w;
    r2[t] = v[t] * v[t];
    __syncthreads();
    for (int off = n >> 1; off > 0; off >>= 1) {
        if (t < off) { r1[t] += r1[t+off]; r2[t] += r2[t+off]; }
        __syncthreads();
    }
    if (t == 0) g_scal[slot] = r1[0] / r2[0];
}

__global__ void k_scalars() {
    float tau = 1.0f / (2.0f * (g_scal[0] + 0.1f * g_scal[1]));
    float lam2 = (tau * 0.1f > 0.1f) ? (0.1f / tau) : 0.1f;
    g_scal[2] = tau;
    g_scal[3] = tau * lam2;
}

// ---------------- fused gradient (R4 core) + prox/momentum epilogue ----------------
// grid (4, 8, 5): z 0..3 = split-K slices of U @ x^T, z==4 = 0.1*DtD@A.
// Last of the 20 blocks per j-stripe applies the update for that 128x64 stripe.
__global__ void __launch_bounds__(256) k_grad(const float* __restrict__ x, float coeff) {
    if (g_done) return;
    __shared__ __align__(16) float Us[2][32][34];
    __shared__ __align__(16) float Xs[2][32][68];
    __shared__ int s_last;
    int z = blockIdx.z;
    int i0 = blockIdx.x * 32, j0 = blockIdx.y * 64;
    int tid = threadIdx.x;
    int ti = tid >> 4, tj = tid & 15;
    int tr = tid >> 5, tc = tid & 31;
    int rr = tid >> 6, cc = tid & 63;
    float acc[2][4] = {};
    int nk = (z < 4) ? 16 : 4;
    float ur[4], xr[8];

    auto load_regs = [&](int kt) {
        if (z < 4) {
            int m0 = z * 512 + kt * 32;
            #pragma unroll
            for (int r = 0; r < 4; r++)
                ur[r] = g_U[(size_t)(i0 + tr + 8*r) * Mdim + m0 + tc];
            #pragma unroll
            for (int r = 0; r < 8; r++)
                xr[r] = x[(size_t)(j0 + tr + 8*r) * Mdim + m0 + tc];
        } else {
            int p0 = kt * 32;
            #pragma unroll
            for (int r = 0; r < 4; r++)
                ur[r] = g_DtD[(i0 + tr + 8*r) * Ldim + p0 + tc];
            #pragma unroll
            for (int r = 0; r < 8; r++)
                xr[r] = g_A[(p0 + rr + 4*r) * Ddim + j0 + cc];
        }
    };
    auto store_smem = [&](int b) {
        #pragma unroll
        for (int r = 0; r < 4; r++) Us[b][tc][tr + 8*r] = ur[r];
        if (z < 4) {
            #pragma unroll
            for (int r = 0; r < 8; r++) Xs[b][tc][tr + 8*r] = xr[r];
        } else {
            #pragma unroll
            for (int r = 0; r < 8; r++) Xs[b][rr + 4*r][cc] = xr[r];
        }
    };

    load_regs(0);
    store_smem(0);
    __syncthreads();
    for (int kt = 0; kt < nk; kt++) {
        int b = kt & 1;
        if (kt + 1 < nk) load_regs(kt + 1);
        float2 av = *(const float2*)&Us[b][0][2*ti];
        float4 bv = *(const float4*)&Xs[b][0][4*tj];
        #pragma unroll
        for (int kk = 0; kk < 32; kk++) {
            float2 av2; float4 bv2;
            if (kk < 31) {
                av2 = *(const float2*)&Us[b][kk+1][2*ti];
                bv2 = *(const float4*)&Xs[b][kk+1][4*tj];
            }
            acc[0][0] += av.x*bv.x; acc[0][1] += av.x*bv.y; acc[0][2] += av.x*bv.z; acc[0][3] += av.x*bv.w;
            acc[1][0] += av.y*bv.x; acc[1][1] += av.y*bv.y; acc[1][2] += av.y*bv.z; acc[1][3] += av.y*bv.w;
            if (kk < 31) { av = av2; bv = bv2; }
        }
        if (kt + 1 < nk) {
            store_smem((kt + 1) & 1);
            __syncthreads();
        }
    }
    float sc = (z == 4) ? 0.1f : 1.0f;
    {
        int i = i0 + 2*ti, j = j0 + 4*tj;
        float* outp = &g_G[z][0];
        #pragma unroll
        for (int r = 0; r < 2; r++)
            #pragma unroll
            for (int c = 0; c < 4; c++)
                outp[(i + r) * Ddim + j + c] = acc[r][c] * sc;
    }

    // ---- stripe-completion gate, then fused prox/momentum update ----
    __threadfence();
    __syncthreads();
    if (tid == 0) s_last = (atomicAdd(&g_cntg[blockIdx.y], 1) == 19) ? 1 : 0;
    __syncthreads();
    if (!s_last) return;
    __threadfence();
    float tau = g_scal[2], thr = g_scal[3];
    int jbase = blockIdx.y * 64;
    for (int e = tid; e < 2048; e += 256) {       // 128 rows x 16 float4s
        int i = e >> 4, c4 = (e & 15) << 2;
        int off = i * Ddim + jbase + c4;
        float4 g0 = *(float4*)&g_G[0][off];
        float4 g1 = *(float4*)&g_G[1][off];
        float4 g2 = *(float4*)&g_G[2][off];
        float4 g3 = *(float4*)&g_G[3][off];
        float4 g4 = *(float4*)&g_G[4][off];
        float4 a  = *(float4*)&g_A[off];
        float4 bm = *(float4*)&g_Bm[off];
        float4 an, bn;
        float g, zv, az;
        g = g0.x + g1.x + g2.x + g3.x + g4.x; zv = bm.x - tau*g; az = fabsf(zv) - thr;
        an.x = (az > 0.f) ? copysignf(az, zv) : 0.f; bn.x = a.x + coeff * (an.x - a.x);
        g = g0.y + g1.y + g2.y + g3.y + g4.y; zv = bm.y - tau*g; az = fabsf(zv) - thr;
        an.y = (az > 0.f) ? copysignf(az, zv) : 0.f; bn.y = a.y + coeff * (an.y - a.y);
        g = g0.z + g1.z + g2.z + g3.z + g4.z; zv = bm.z - tau*g; az = fabsf(zv) - thr;
        an.z = (az > 0.f) ? copysignf(az, zv) : 0.f; bn.z = a.z + coeff * (an.z - a.z);
        g = g0.w + g1.w + g2.w + g3.w + g4.w; zv = bm.w - tau*g; az = fabsf(zv) - thr;
        an.w = (az > 0.f) ? copysignf(az, zv) : 0.f; bn.w = a.w + coeff * (an.w - a.w);
        *(float4*)&g_A[off]  = an;
        *(float4*)&g_Bm[off] = bn;
    }
    __syncthreads();
    if (tid == 0) g_cntg[blockIdx.y] = 0;   // reset for next iteration / replay
}

// ---------------- fused forward (R4 core): T = A@x, U = mask*(T-py) + conv ----------------
__global__ void __launch_bounds__(256) k_fwd(const float* __restrict__ x,
                                             const float* __restrict__ py,
                                             const float* __restrict__ mask) {
    if (g_done) return;
    __shared__ __align__(16) float As[2][32][34];
    __shared__ __align__(16) float Xs[2][32][68];
    __shared__ int s_last;
    __shared__ float s_diag[128], s_r1[128], s_r2[128];
    int i0 = blockIdx.x * 32, m0 = blockIdx.y * 64;
    int tid = threadIdx.x;
    int ti = tid >> 4, tj = tid & 15;
    int tr = tid >> 5, tc = tid & 31;
    int rr = tid >> 6, cc = tid & 63;
    float acc[2][4] = {};
    float ar[4], xr[8];

    auto load_regs = [&](int kt) {
        int k0 = kt * 32;
        #pragma unroll
        for (int r = 0; r < 4; r++)
            ar[r] = g_A[(i0 + tr + 8*r) * Ddim + k0 + tc];
        #pragma unroll
        for (int r = 0; r < 8; r++)
            xr[r] = x[(size_t)(k0 + rr + 4*r) * Mdim + m0 + cc];
    };
    auto store_smem = [&](int b) {
        #pragma unroll
        for (int r = 0; r < 4; r++) As[b][tc][tr + 8*r] = ar[r];
        #pragma unroll
        for (int r = 0; r < 8; r++) Xs[b][rr + 4*r][cc] = xr[r];
    };

    load_regs(0);
    store_smem(0);
    __syncthreads();
    for (int kt = 0; kt < 16; kt++) {
        int b = kt & 1;
        if (kt + 1 < 16) load_regs(kt + 1);
        float2 av = *(const float2*)&As[b][0][2*ti];
        float4 bv = *(const float4*)&Xs[b][0][4*tj];
        #pragma unroll
        for (int kk = 0; kk < 32; kk++) {
            float2 av2; float4 bv2;
            if (kk < 31) {
                av2 = *(const float2*)&As[b][kk+1][2*ti];
                bv2 = *(const float4*)&Xs[b][kk+1][4*tj];
            }
            acc[0][0] += av.x*bv.x; acc[0][1] += av.x*bv.y; acc[0][2] += av.x*bv.z; acc[0][3] += av.x*bv.w;
            acc[1][0] += av.y*bv.x; acc[1][1] += av.y*bv.y; acc[1][2] += av.y*bv.z; acc[1][3] += av.y*bv.w;
            if (kk < 31) { av = av2; bv = bv2; }
        }
        if (kt + 1 < 16) {
            store_smem((kt + 1) & 1);
            __syncthreads();
        }
    }
    #pragma unroll
    for (int r = 0; r < 2; r++) {
        int i = i0 + 2*ti + r;
        #pragma unroll
        for (int c = 0; c < 4; c++) {
            int m = m0 + 4*tj + c;
            size_t o = (size_t)i * Mdim + m;
            float t = acc[r][c];
            g_T[o] = t;
            g_U[o] = mask[o] * (t - py[o]);
        }
    }

    // ---- last finishing block (of 128) runs the Hankel-tail convergence check ----
    __threadfence();
    __syncthreads();
    if (tid == 0) s_last = (atomicAdd(&g_cntf, 1) == 127) ? 1 : 0;
    __syncthreads();
    if (!s_last) return;
    __threadfence();
    float sum = 0.f, yv = 0.f;
    if (tid < NTAIL) {
        for (int i = tid + 1; i < Ldim; i++) sum += g_T[i * Mdim + (Mdim + tid - i)];
        sum /= (float)(NTAIL - tid);
        yv = g_ytail[tid];
    }
    if (tid < 128) {
        float d = (tid < NTAIL) ? (yv - sum) : 0.f;
        s_diag[tid] = sum;
        s_r1[tid] = d * d;
        s_r2[tid] = (tid < NTAIL) ? yv * yv : 0.f;
    }
    __syncthreads();
    for (int off = 64; off > 0; off >>= 1) {
        if (tid < off) { s_r1[tid] += s_r1[tid + off]; s_r2[tid] += s_r2[tid + off]; }
        __syncthreads();
    }
    if (tid == 0) {
        if (sqrtf(s_r1[0] / s_r2[0]) <= 1e-5f) g_done = 1;
        g_cntf = 0;
    }
    if (tid < NTAIL) g_ytail[tid] = s_diag[tid];
}

// ---------------- output: (A@x, A) ----------------
__global__ void k_output(float* __restrict__ out, int out_size) {
    int idx = blockIdx.x * blockDim.x + threadIdx.x;
    if (idx >= out_size) return;
    if (idx < Ldim*Mdim) out[idx] = g_T[idx];
    else if (idx < Ldim*Mdim + Ldim*Ddim) out[idx] = g_A[idx - Ldim*Mdim];
}

extern "C" void kernel_launch(void* const* d_in, const int* in_sizes, int n_in,
                              void* d_out, int out_size) {
    const float* x    = (const float*)d_in[0];
    const float* py   = (const float*)d_in[1];
    const float* mask = (const float*)d_in[2];
    const float* y0   = (const float*)d_in[3];
    float* outp = (float*)d_out;

    void *pS, *pP0, *pP1, *pDtD, *pQ0, *pQ1;
    cudaGetSymbolAddress(&pS,   g_S);
    cudaGetSymbolAddress(&pP0,  g_P0);
    cudaGetSymbolAddress(&pP1,  g_P1);
    cudaGetSymbolAddress(&pDtD, g_DtD);
    cudaGetSymbolAddress(&pQ0,  g_Q0);
    cudaGetSymbolAddress(&pQ1,  g_Q1);

    k_init<<<(Ldim*Mdim + 255)/256, 256>>>(mask, py, y0);
    k_delta<<<(Ldim*Ldim + 255)/256, 256>>>();
    k_dtd<<<(Ldim*Ldim + 255)/256, 256>>>();

    // maxeig(x x^T): 10 trace-normalized squarings + Rayleigh
    gemm_nt<<<dim3(16,16), 256>>>(x, x, (float*)pS, Ddim, Mdim);
    k_trace<<<1, 512>>>((const float*)pS, Ddim);
    k_normmat<<<(Ddim*Ddim + 255)/256, 256>>>((const float*)pS, (float*)pP0, Ddim*Ddim);
    for (int i = 0; i < 10; i++) {
        gemm_nt<<<dim3(16,16), 256>>>((const float*)pP0, (const float*)pP0, (float*)pP1, Ddim, Ddim);
        k_trace<<<1, 512>>>((const float*)pP1, Ddim);
        k_normmat<<<(Ddim*Ddim + 255)/256, 256>>>((const float*)pP1, (float*)pP0, Ddim*Ddim);
    }
    k_rayleigh<<<1, Ddim>>>((const float*)pP0, (const float*)pS, Ddim, 0);

    // maxeig(DtD): 17 trace-normalized squarings + Rayleigh
    k_trace<<<1, 512>>>((const float*)pDtD, Ldim);
    k_normmat<<<(Ldim*Ldim + 255)/256, 256>>>((const float*)pDtD, (float*)pQ0, Ldim*Ldim);
    for (int i = 0; i < 17; i++) {
        gemm_nt<<<dim3(4,4), 256>>>((const float*)pQ0, (const float*)pQ0, (float*)pQ1, Ldim, Ldim);
        k_trace<<<1, 512>>>((const float*)pQ1, Ldim);
        k_normmat<<<(Ldim*Ldim + 255)/256, 256>>>((const float*)pQ1, (float*)pQ0, Ldim*Ldim);
    }
    k_rayleigh<<<1, Ldim>>>((const float*)pQ0, (const float*)pDtD, Ldim, 1);

    k_scalars<<<1, 1>>>();

    // FISTA loop: 2 fused kernels per iteration, device-side early exit
    float a = 1.0f;
    for (int it = 0; it < 200; it++) {
        float anew = (1.0f + sqrtf(1.0f + 4.0f * a * a)) * 0.5f;
        float coeff = (a - 1.0f) / anew;
        a = anew;
        k_grad<<<dim3(4, 8, 5), 256>>>(x, coeff);
        k_fwd<<<dim3(4, 32), 256>>>(x, py, mask);
    }

    k_output<<<(out_size + 255)/256, 256>>>(outp, out_size);
}